// round 8
// baseline (speedup 1.0000x reference)
#include <cuda_runtime.h>
#include <cuda_bf16.h>

#define N_NODES 100000
#define N_EDGES 3200000
#define IN_DIM 128
#define HID 64
#define N_GRAPHS 64
#define BN_EPS 1e-5f

// ---------------- scratch ----------------
__device__ __align__(16) float g_dinv[N_NODES];
__device__ __align__(16) int   g_count[N_NODES];
__device__ __align__(16) int   g_off[N_NODES + 1];
__device__ __align__(16) int   g_cursor[N_NODES];
__device__ __align__(16) float2 g_csr[N_EDGES];       // {src_as_float, norm}
__device__ __align__(16) float g_h[N_NODES * HID];    // gemm1 out
__device__ __align__(16) float g_h2[N_NODES * HID];   // gemm2 out
__device__ __align__(16) float g_agg[N_NODES * HID];  // aggregation out
__device__ double g_stats[4 * HID];
__device__ float g_A1[HID], g_B1[HID], g_A2[HID], g_B2[HID];
__device__ float g_pool[N_GRAPHS * HID];
__device__ float g_cnt[N_GRAPHS];

// ---------------- init ----------------
__global__ void init_kernel() {
    int t = blockIdx.x * blockDim.x + threadIdx.x;
    if (t < N_NODES) { g_dinv[t] = 1.0f; g_count[t] = 0; }
    if (t < 4 * HID) g_stats[t] = 0.0;
    if (t < N_GRAPHS * HID) g_pool[t] = 0.0f;
    if (t < N_GRAPHS) g_cnt[t] = 0.0f;
}

// ---------------- weighted degree + edge histogram ----------------
__global__ void deg_count_kernel(const int* __restrict__ col,
                                 const float* __restrict__ w) {
    int e = blockIdx.x * blockDim.x + threadIdx.x;
    if (e < N_EDGES) {
        int c = col[e];
        atomicAdd(&g_dinv[c], w[e]);
        atomicAdd(&g_count[c], 1);
    }
}

__global__ void rsqrt_kernel() {
    int i = blockIdx.x * blockDim.x + threadIdx.x;
    if (i < N_NODES) g_dinv[i] = rsqrtf(g_dinv[i]);
}

// ---------------- single-block exclusive scan over counts ----------------
__global__ void scan_kernel() {
    const int T = 1024;
    const int CH = (N_NODES + T - 1) / T;  // 98
    int t = threadIdx.x;
    int base = t * CH;
    int sum = 0;
    for (int i = 0; i < CH; i++) {
        int idx = base + i;
        if (idx < N_NODES) sum += g_count[idx];
    }
    __shared__ int sh[T];
    sh[t] = sum;
    __syncthreads();
    // Hillis-Steele inclusive scan
    for (int off = 1; off < T; off <<= 1) {
        int v = (t >= off) ? sh[t - off] : 0;
        __syncthreads();
        sh[t] += v;
        __syncthreads();
    }
    int run = sh[t] - sum;  // exclusive prefix for this chunk
    for (int i = 0; i < CH; i++) {
        int idx = base + i;
        if (idx < N_NODES) {
            g_off[idx] = run;
            g_cursor[idx] = run;
            run += g_count[idx];
        }
    }
    if (t == T - 1) g_off[N_NODES] = run;
}

// ---------------- CSR fill (packed {src, norm}, single 8B store) ----------
__global__ void fill_kernel(const int* __restrict__ row,
                            const int* __restrict__ col,
                            const float* __restrict__ w) {
    int e = blockIdx.x * blockDim.x + threadIdx.x;
    if (e >= N_EDGES) return;
    int r = row[e];
    int c = col[e];
    int pos = atomicAdd(&g_cursor[c], 1);
    g_csr[pos] = make_float2(__int_as_float(r), g_dinv[r] * w[e] * g_dinv[c]);
}

// ---------------- register-blocked GEMM: out[n,64] = X[n,K] @ W[K,64] ----
// WHICH==0: X = Xin (external), out = g_h
// WHICH==1: X = relu(A1*g_agg+B1)  (fused BN1+ReLU), out = g_h2
// 256 threads, tile 32 rows x 64 cols, 8 outputs/thread. 100000 % 32 == 0.
template <int K, int WHICH>
__global__ void gemm_kernel(const float* __restrict__ Xin,
                            const float* __restrict__ W) {
    __shared__ float sX[32][K];
    __shared__ float sW[K * 64];
    const float* X = WHICH ? (const float*)g_agg : Xin;
    float* out = WHICH ? g_h2 : g_h;
    int tid = threadIdx.x;
    int node0 = blockIdx.x * 32;
    for (int i = tid; i < K * 64; i += 256) sW[i] = W[i];
    for (int i = tid; i < 32 * K; i += 256) {
        int r = i / K, c = i % K;
        float v = X[(size_t)(node0 + r) * K + c];
        if (WHICH) v = fmaxf(fmaf(g_A1[c], v, g_B1[c]), 0.0f);
        sX[r][c] = v;
    }
    __syncthreads();
    int c2 = (tid & 31) * 2;   // column pair
    int rg = tid >> 5;         // 0..7 -> rows rg, rg+8, rg+16, rg+24
    float a0x = 0, a0y = 0, a1x = 0, a1y = 0, a2x = 0, a2y = 0, a3x = 0, a3y = 0;
#pragma unroll
    for (int k = 0; k < K; k++) {
        float2 wv = *(const float2*)&sW[k * 64 + c2];
        float x0 = sX[rg][k];
        float x1 = sX[rg + 8][k];
        float x2 = sX[rg + 16][k];
        float x3 = sX[rg + 24][k];
        a0x = fmaf(x0, wv.x, a0x); a0y = fmaf(x0, wv.y, a0y);
        a1x = fmaf(x1, wv.x, a1x); a1y = fmaf(x1, wv.y, a1y);
        a2x = fmaf(x2, wv.x, a2x); a2y = fmaf(x2, wv.y, a2y);
        a3x = fmaf(x3, wv.x, a3x); a3y = fmaf(x3, wv.y, a3y);
    }
    float2* o = (float2*)out;
    o[((size_t)(node0 + rg) * 64 + c2) / 2]      = make_float2(a0x, a0y);
    o[((size_t)(node0 + rg + 8) * 64 + c2) / 2]  = make_float2(a1x, a1y);
    o[((size_t)(node0 + rg + 16) * 64 + c2) / 2] = make_float2(a2x, a2y);
    o[((size_t)(node0 + rg + 24) * 64 + c2) / 2] = make_float2(a3x, a3y);
}

// ---------------- CSR gather-aggregate (no atomics, 4-way MLP) ------------
// agg[n,j] = dinv[n]^2 * h[n,j] + b[j] + sum_{k in nbrs(n)} norm[k]*h[src[k],j]
__global__ void aggregate_kernel(const float* __restrict__ b, int which) {
    const float* h = which ? g_h2 : g_h;
    int node = blockIdx.x * 4 + (threadIdx.x >> 6);  // 4 nodes / 256-thread block
    int j = threadIdx.x & 63;
    float d = g_dinv[node];
    float acc = fmaf(d * d, h[(size_t)node * HID + j], b[j]);
    int s = g_off[node];
    int e = g_off[node + 1];
    int k = s;
    for (; k + 3 < e; k += 4) {
        float2 p0 = g_csr[k];
        float2 p1 = g_csr[k + 1];
        float2 p2 = g_csr[k + 2];
        float2 p3 = g_csr[k + 3];
        // issue all 4 gathers before consuming (MLP=4)
        float h0 = h[(size_t)__float_as_int(p0.x) * HID + j];
        float h1 = h[(size_t)__float_as_int(p1.x) * HID + j];
        float h2 = h[(size_t)__float_as_int(p2.x) * HID + j];
        float h3 = h[(size_t)__float_as_int(p3.x) * HID + j];
        acc = fmaf(p0.y, h0, acc);
        acc = fmaf(p1.y, h1, acc);
        acc = fmaf(p2.y, h2, acc);
        acc = fmaf(p3.y, h3, acc);
    }
    for (; k < e; k++) {
        float2 p = g_csr[k];
        acc = fmaf(p.y, h[(size_t)__float_as_int(p.x) * HID + j], acc);
    }
    g_agg[(size_t)node * HID + j] = acc;
}

// ---------------- BN stats ----------------
__global__ void stats_kernel(int off) {
    int j = threadIdx.x & 63;
    int g = threadIdx.x >> 6;
    int r0 = blockIdx.x * 512;
    int rend = min(r0 + 512, N_NODES);
    float s = 0.0f, s2 = 0.0f;
    for (int r = r0 + g; r < rend; r += 4) {
        float v = g_agg[(size_t)r * 64 + j];
        s += v;
        s2 = fmaf(v, v, s2);
    }
    __shared__ float sh[256], sh2[256];
    sh[threadIdx.x] = s;
    sh2[threadIdx.x] = s2;
    __syncthreads();
    if (g == 0) {
        s = sh[j] + sh[64 + j] + sh[128 + j] + sh[192 + j];
        s2 = sh2[j] + sh2[64 + j] + sh2[128 + j] + sh2[192 + j];
        atomicAdd(&g_stats[off + j], (double)s);
        atomicAdd(&g_stats[off + 64 + j], (double)s2);
    }
}

__global__ void finalize_kernel(const float* __restrict__ gamma,
                                const float* __restrict__ beta,
                                int off, int layer) {
    int j = threadIdx.x;
    double mean = g_stats[off + j] / (double)N_NODES;
    double var = g_stats[off + 64 + j] / (double)N_NODES - mean * mean;
    float istd = rsqrtf((float)var + BN_EPS);
    float a = gamma[j] * istd;
    float bb = beta[j] - a * (float)mean;
    if (layer == 0) { g_A1[j] = a; g_B1[j] = bb; }
    else            { g_A2[j] = a; g_B2[j] = bb; }
}

// ---------------- fused BN2+ReLU + segment-sum pool (batch sorted) --------
__global__ void pool_kernel(const int* __restrict__ batch) {
    int j = threadIdx.x;
    int r0 = blockIdx.x * 128;
    int rend = min(r0 + 128, N_NODES);
    if (r0 >= N_NODES) return;
    float A = g_A2[j], B = g_B2[j];
    int cur = batch[r0];
    float s = 0.0f;
    int c = 0;
    for (int r = r0; r < rend; r++) {
        int gg = batch[r];
        if (gg != cur) {
            atomicAdd(&g_pool[cur * 64 + j], s);
            if (j == 0) atomicAdd(&g_cnt[cur], (float)c);
            s = 0.0f; c = 0; cur = gg;
        }
        float v = fmaxf(fmaf(A, g_agg[(size_t)r * 64 + j], B), 0.0f);
        s += v;
        c++;
    }
    atomicAdd(&g_pool[cur * 64 + j], s);
    if (j == 0) atomicAdd(&g_cnt[cur], (float)c);
}

// ---------------- output head ----------------
__global__ void out_kernel(const float* __restrict__ Wout,
                           const float* __restrict__ bout,
                           float* __restrict__ out) {
    int g = threadIdx.x;
    float c = fmaxf(g_cnt[g], 1.0f);
    float s = 0.0f;
#pragma unroll
    for (int j = 0; j < HID; j++) s = fmaf(g_pool[g * HID + j], Wout[j], s);
    out[g] = s / c + bout[0];
}

// ---------------- launch ----------------
extern "C" void kernel_launch(void* const* d_in, const int* in_sizes, int n_in,
                              void* d_out, int out_size) {
    const float* x = (const float*)d_in[0];
    const int* ei = (const int*)d_in[1];
    const float* ew = (const float*)d_in[2];
    const int* batch = (const int*)d_in[3];
    const float* W1 = (const float*)d_in[4];
    const float* b1 = (const float*)d_in[5];
    const float* W2 = (const float*)d_in[6];
    const float* b2 = (const float*)d_in[7];
    const float* g1 = (const float*)d_in[8];
    const float* be1 = (const float*)d_in[9];
    const float* g2 = (const float*)d_in[10];
    const float* be2 = (const float*)d_in[11];
    const float* Wout = (const float*)d_in[12];
    const float* bout = (const float*)d_in[13];
    float* out = (float*)d_out;

    const int* row = ei;
    const int* col = ei + N_EDGES;

    const int EB = (N_EDGES + 255) / 256;
    const int NB = (N_NODES + 255) / 256;
    const int SB = (N_NODES + 511) / 512;
    const int PB = (N_NODES + 127) / 128;
    const int GB = N_NODES / 32;   // 3125, exact
    const int AB = N_NODES / 4;    // 25000, exact

    // ---- CSR build (once, reused by both layers) ----
    init_kernel<<<NB, 256>>>();
    deg_count_kernel<<<EB, 256>>>(col, ew);
    rsqrt_kernel<<<NB, 256>>>();
    scan_kernel<<<1, 1024>>>();
    fill_kernel<<<EB, 256>>>(row, col, ew);

    // ---- layer 1 ----
    gemm_kernel<IN_DIM, 0><<<GB, 256>>>(x, W1);
    aggregate_kernel<<<AB, 256>>>(b1, 0);
    stats_kernel<<<SB, 256>>>(0);
    finalize_kernel<<<1, 64>>>(g1, be1, 0, 0);

    // ---- layer 2 (BN1+ReLU fused into GEMM X-load) ----
    gemm_kernel<HID, 1><<<GB, 256>>>(x /*unused*/, W2);
    aggregate_kernel<<<AB, 256>>>(b2, 1);
    stats_kernel<<<SB, 256>>>(128);
    finalize_kernel<<<1, 64>>>(g2, be2, 128, 1);

    // ---- pool + head ----
    pool_kernel<<<PB, 64>>>(batch);
    out_kernel<<<1, 64>>>(Wout, bout, out);
}

// round 9
// speedup vs baseline: 1.2759x; 1.2759x over previous
#include <cuda_runtime.h>
#include <cuda_bf16.h>

#define N_NODES 100000
#define N_EDGES 3200000
#define IN_DIM 128
#define HID 64
#define N_GRAPHS 64
#define BN_EPS 1e-5f

#define SCAN_NBLK 98   // ceil(100000 / 1024)

// ---------------- scratch ----------------
__device__ __align__(16) float g_dinv[N_NODES];
__device__ __align__(16) int   g_count[N_NODES];
__device__ __align__(16) int   g_off[N_NODES + 1];
__device__ __align__(16) int   g_cursor[N_NODES];
__device__ __align__(16) int   g_blocksum[SCAN_NBLK];
__device__ __align__(16) int   g_blockoff[SCAN_NBLK];
__device__ __align__(16) float2 g_csr[N_EDGES];       // {src_as_float, norm}
__device__ __align__(16) float g_h[N_NODES * HID];    // gemm1 out
__device__ __align__(16) float g_h2[N_NODES * HID];   // gemm2 out
__device__ __align__(16) float g_agg[N_NODES * HID];  // aggregation out
__device__ double g_stats[4 * HID];
__device__ float g_A1[HID], g_B1[HID], g_A2[HID], g_B2[HID];
__device__ float g_pool[N_GRAPHS * HID];
__device__ float g_cnt[N_GRAPHS];

// ---------------- init ----------------
__global__ void init_kernel() {
    int t = blockIdx.x * blockDim.x + threadIdx.x;
    if (t < N_NODES) { g_dinv[t] = 1.0f; g_count[t] = 0; }
    if (t < 4 * HID) g_stats[t] = 0.0;
    if (t < N_GRAPHS * HID) g_pool[t] = 0.0f;
    if (t < N_GRAPHS) g_cnt[t] = 0.0f;
    if (t == 0) g_off[N_NODES] = N_EDGES;  // counts always sum to N_EDGES
}

// ---------------- weighted degree + edge histogram ----------------
__global__ void deg_count_kernel(const int* __restrict__ col,
                                 const float* __restrict__ w) {
    int e = blockIdx.x * blockDim.x + threadIdx.x;
    if (e < N_EDGES) {
        int c = col[e];
        atomicAdd(&g_dinv[c], w[e]);
        atomicAdd(&g_count[c], 1);
    }
}

__global__ void rsqrt_kernel() {
    int i = blockIdx.x * blockDim.x + threadIdx.x;
    if (i < N_NODES) g_dinv[i] = rsqrtf(g_dinv[i]);
}

// ---------------- parallel 3-phase exclusive scan over counts -------------
// Phase A: per-block (1024-element chunk) reduction -> g_blocksum
__global__ void scan_phaseA() {
    int blk = blockIdx.x;
    int tid = threadIdx.x;  // 256 threads
    int base = blk * 1024 + tid * 4;
    int s = 0;
#pragma unroll
    for (int i = 0; i < 4; i++) {
        int idx = base + i;
        if (idx < N_NODES) s += g_count[idx];
    }
    __shared__ int sh[256];
    sh[tid] = s;
    __syncthreads();
    for (int off = 128; off > 0; off >>= 1) {
        if (tid < off) sh[tid] += sh[tid + off];
        __syncthreads();
    }
    if (tid == 0) g_blocksum[blk] = sh[0];
}

// Phase B: single block scans the 98 block sums -> exclusive g_blockoff
__global__ void scan_phaseB() {
    int t = threadIdx.x;  // 128 threads
    int v = (t < SCAN_NBLK) ? g_blocksum[t] : 0;
    __shared__ int sh[128];
    sh[t] = v;
    __syncthreads();
    for (int off = 1; off < 128; off <<= 1) {
        int u = (t >= off) ? sh[t - off] : 0;
        __syncthreads();
        sh[t] += u;
        __syncthreads();
    }
    if (t < SCAN_NBLK) g_blockoff[t] = sh[t] - v;
}

// Phase C: per-block local exclusive scan + block offset -> g_off, g_cursor
__global__ void scan_phaseC() {
    int blk = blockIdx.x;
    int tid = threadIdx.x;  // 256 threads
    int base = blk * 1024 + tid * 4;
    int c0 = 0, c1 = 0, c2 = 0, c3 = 0;
    if (base + 0 < N_NODES) c0 = g_count[base + 0];
    if (base + 1 < N_NODES) c1 = g_count[base + 1];
    if (base + 2 < N_NODES) c2 = g_count[base + 2];
    if (base + 3 < N_NODES) c3 = g_count[base + 3];
    int s = c0 + c1 + c2 + c3;
    __shared__ int sh[256];
    sh[tid] = s;
    __syncthreads();
    for (int off = 1; off < 256; off <<= 1) {
        int u = (tid >= off) ? sh[tid - off] : 0;
        __syncthreads();
        sh[tid] += u;
        __syncthreads();
    }
    int run = g_blockoff[blk] + sh[tid] - s;  // exclusive prefix
    if (base + 0 < N_NODES) { g_off[base + 0] = run; g_cursor[base + 0] = run; run += c0; }
    if (base + 1 < N_NODES) { g_off[base + 1] = run; g_cursor[base + 1] = run; run += c1; }
    if (base + 2 < N_NODES) { g_off[base + 2] = run; g_cursor[base + 2] = run; run += c2; }
    if (base + 3 < N_NODES) { g_off[base + 3] = run; g_cursor[base + 3] = run; run += c3; }
}

// ---------------- CSR fill (packed {src, norm}, single 8B store) ----------
__global__ void fill_kernel(const int* __restrict__ row,
                            const int* __restrict__ col,
                            const float* __restrict__ w) {
    int e = blockIdx.x * blockDim.x + threadIdx.x;
    if (e >= N_EDGES) return;
    int r = row[e];
    int c = col[e];
    int pos = atomicAdd(&g_cursor[c], 1);
    g_csr[pos] = make_float2(__int_as_float(r), g_dinv[r] * w[e] * g_dinv[c]);
}

// ---------------- register-blocked GEMM: out[n,64] = X[n,K] @ W[K,64] ----
// WHICH==0: X = Xin (external), out = g_h
// WHICH==1: X = relu(A1*g_agg+B1)  (fused BN1+ReLU), out = g_h2
template <int K, int WHICH>
__global__ void gemm_kernel(const float* __restrict__ Xin,
                            const float* __restrict__ W) {
    __shared__ float sX[32][K];
    __shared__ float sW[K * 64];
    const float* X = WHICH ? (const float*)g_agg : Xin;
    float* out = WHICH ? g_h2 : g_h;
    int tid = threadIdx.x;
    int node0 = blockIdx.x * 32;
    for (int i = tid; i < K * 64; i += 256) sW[i] = W[i];
    for (int i = tid; i < 32 * K; i += 256) {
        int r = i / K, c = i % K;
        float v = X[(size_t)(node0 + r) * K + c];
        if (WHICH) v = fmaxf(fmaf(g_A1[c], v, g_B1[c]), 0.0f);
        sX[r][c] = v;
    }
    __syncthreads();
    int c2 = (tid & 31) * 2;   // column pair
    int rg = tid >> 5;         // 0..7 -> rows rg, rg+8, rg+16, rg+24
    float a0x = 0, a0y = 0, a1x = 0, a1y = 0, a2x = 0, a2y = 0, a3x = 0, a3y = 0;
#pragma unroll
    for (int k = 0; k < K; k++) {
        float2 wv = *(const float2*)&sW[k * 64 + c2];
        float x0 = sX[rg][k];
        float x1 = sX[rg + 8][k];
        float x2 = sX[rg + 16][k];
        float x3 = sX[rg + 24][k];
        a0x = fmaf(x0, wv.x, a0x); a0y = fmaf(x0, wv.y, a0y);
        a1x = fmaf(x1, wv.x, a1x); a1y = fmaf(x1, wv.y, a1y);
        a2x = fmaf(x2, wv.x, a2x); a2y = fmaf(x2, wv.y, a2y);
        a3x = fmaf(x3, wv.x, a3x); a3y = fmaf(x3, wv.y, a3y);
    }
    float2* o = (float2*)out;
    o[((size_t)(node0 + rg) * 64 + c2) / 2]      = make_float2(a0x, a0y);
    o[((size_t)(node0 + rg + 8) * 64 + c2) / 2]  = make_float2(a1x, a1y);
    o[((size_t)(node0 + rg + 16) * 64 + c2) / 2] = make_float2(a2x, a2y);
    o[((size_t)(node0 + rg + 24) * 64 + c2) / 2] = make_float2(a3x, a3y);
}

// ---------------- CSR gather-aggregate (no atomics, 4-way MLP) ------------
__global__ void aggregate_kernel(const float* __restrict__ b, int which) {
    const float* h = which ? g_h2 : g_h;
    int node = blockIdx.x * 4 + (threadIdx.x >> 6);  // 4 nodes / 256-thread block
    int j = threadIdx.x & 63;
    float d = g_dinv[node];
    float acc = fmaf(d * d, h[(size_t)node * HID + j], b[j]);
    int s = g_off[node];
    int e = g_off[node + 1];
    int k = s;
    for (; k + 3 < e; k += 4) {
        float2 p0 = g_csr[k];
        float2 p1 = g_csr[k + 1];
        float2 p2 = g_csr[k + 2];
        float2 p3 = g_csr[k + 3];
        float h0 = h[(size_t)__float_as_int(p0.x) * HID + j];
        float h1 = h[(size_t)__float_as_int(p1.x) * HID + j];
        float h2 = h[(size_t)__float_as_int(p2.x) * HID + j];
        float h3 = h[(size_t)__float_as_int(p3.x) * HID + j];
        acc = fmaf(p0.y, h0, acc);
        acc = fmaf(p1.y, h1, acc);
        acc = fmaf(p2.y, h2, acc);
        acc = fmaf(p3.y, h3, acc);
    }
    for (; k < e; k++) {
        float2 p = g_csr[k];
        acc = fmaf(p.y, h[(size_t)__float_as_int(p.x) * HID + j], acc);
    }
    g_agg[(size_t)node * HID + j] = acc;
}

// ---------------- BN stats ----------------
__global__ void stats_kernel(int off) {
    int j = threadIdx.x & 63;
    int g = threadIdx.x >> 6;
    int r0 = blockIdx.x * 512;
    int rend = min(r0 + 512, N_NODES);
    float s = 0.0f, s2 = 0.0f;
    for (int r = r0 + g; r < rend; r += 4) {
        float v = g_agg[(size_t)r * 64 + j];
        s += v;
        s2 = fmaf(v, v, s2);
    }
    __shared__ float sh[256], sh2[256];
    sh[threadIdx.x] = s;
    sh2[threadIdx.x] = s2;
    __syncthreads();
    if (g == 0) {
        s = sh[j] + sh[64 + j] + sh[128 + j] + sh[192 + j];
        s2 = sh2[j] + sh2[64 + j] + sh2[128 + j] + sh2[192 + j];
        atomicAdd(&g_stats[off + j], (double)s);
        atomicAdd(&g_stats[off + 64 + j], (double)s2);
    }
}

__global__ void finalize_kernel(const float* __restrict__ gamma,
                                const float* __restrict__ beta,
                                int off, int layer) {
    int j = threadIdx.x;
    double mean = g_stats[off + j] / (double)N_NODES;
    double var = g_stats[off + 64 + j] / (double)N_NODES - mean * mean;
    float istd = rsqrtf((float)var + BN_EPS);
    float a = gamma[j] * istd;
    float bb = beta[j] - a * (float)mean;
    if (layer == 0) { g_A1[j] = a; g_B1[j] = bb; }
    else            { g_A2[j] = a; g_B2[j] = bb; }
}

// ---------------- fused BN2+ReLU + segment-sum pool (batch sorted) --------
__global__ void pool_kernel(const int* __restrict__ batch) {
    int j = threadIdx.x;
    int r0 = blockIdx.x * 128;
    int rend = min(r0 + 128, N_NODES);
    if (r0 >= N_NODES) return;
    float A = g_A2[j], B = g_B2[j];
    int cur = batch[r0];
    float s = 0.0f;
    int c = 0;
    for (int r = r0; r < rend; r++) {
        int gg = batch[r];
        if (gg != cur) {
            atomicAdd(&g_pool[cur * 64 + j], s);
            if (j == 0) atomicAdd(&g_cnt[cur], (float)c);
            s = 0.0f; c = 0; cur = gg;
        }
        float v = fmaxf(fmaf(A, g_agg[(size_t)r * 64 + j], B), 0.0f);
        s += v;
        c++;
    }
    atomicAdd(&g_pool[cur * 64 + j], s);
    if (j == 0) atomicAdd(&g_cnt[cur], (float)c);
}

// ---------------- output head ----------------
__global__ void out_kernel(const float* __restrict__ Wout,
                           const float* __restrict__ bout,
                           float* __restrict__ out) {
    int g = threadIdx.x;
    float c = fmaxf(g_cnt[g], 1.0f);
    float s = 0.0f;
#pragma unroll
    for (int j = 0; j < HID; j++) s = fmaf(g_pool[g * HID + j], Wout[j], s);
    out[g] = s / c + bout[0];
}

// ---------------- launch ----------------
extern "C" void kernel_launch(void* const* d_in, const int* in_sizes, int n_in,
                              void* d_out, int out_size) {
    const float* x = (const float*)d_in[0];
    const int* ei = (const int*)d_in[1];
    const float* ew = (const float*)d_in[2];
    const int* batch = (const int*)d_in[3];
    const float* W1 = (const float*)d_in[4];
    const float* b1 = (const float*)d_in[5];
    const float* W2 = (const float*)d_in[6];
    const float* b2 = (const float*)d_in[7];
    const float* g1 = (const float*)d_in[8];
    const float* be1 = (const float*)d_in[9];
    const float* g2 = (const float*)d_in[10];
    const float* be2 = (const float*)d_in[11];
    const float* Wout = (const float*)d_in[12];
    const float* bout = (const float*)d_in[13];
    float* out = (float*)d_out;

    const int* row = ei;
    const int* col = ei + N_EDGES;

    const int EB = (N_EDGES + 255) / 256;
    const int NB = (N_NODES + 255) / 256;
    const int SB = (N_NODES + 511) / 512;
    const int PB = (N_NODES + 127) / 128;
    const int GB = N_NODES / 32;   // 3125, exact
    const int AB = N_NODES / 4;    // 25000, exact

    // ---- CSR build (once, reused by both layers) ----
    init_kernel<<<NB, 256>>>();
    deg_count_kernel<<<EB, 256>>>(col, ew);
    rsqrt_kernel<<<NB, 256>>>();
    scan_phaseA<<<SCAN_NBLK, 256>>>();
    scan_phaseB<<<1, 128>>>();
    scan_phaseC<<<SCAN_NBLK, 256>>>();
    fill_kernel<<<EB, 256>>>(row, col, ew);

    // ---- layer 1 ----
    gemm_kernel<IN_DIM, 0><<<GB, 256>>>(x, W1);
    aggregate_kernel<<<AB, 256>>>(b1, 0);
    stats_kernel<<<SB, 256>>>(0);
    finalize_kernel<<<1, 64>>>(g1, be1, 0, 0);

    // ---- layer 2 (BN1+ReLU fused into GEMM X-load) ----
    gemm_kernel<HID, 1><<<GB, 256>>>(x /*unused*/, W2);
    aggregate_kernel<<<AB, 256>>>(b2, 1);
    stats_kernel<<<SB, 256>>>(128);
    finalize_kernel<<<1, 64>>>(g2, be2, 128, 1);

    // ---- pool + head ----
    pool_kernel<<<PB, 64>>>(batch);
    out_kernel<<<1, 64>>>(Wout, bout, out);
}